// round 14
// baseline (speedup 1.0000x reference)
#include <cuda_runtime.h>
#include <stdint.h>

#define TT 32
#define NB 4
#define FRAMES (TT*NB)

#define C0 128
#define H0 16
#define W0 16
#define C1 64
#define H1 31
#define W1 31
#define C2 32
#define H2 61
#define W2 61
#define C3 2
#define H3 121
#define W3 121

#define P0 (H0*W0)     // 256
#define P1 (H1*W1)     // 961
#define P2 (H2*W2)     // 3721
#define P3 (H3*W3)     // 14641

typedef unsigned long long u64;

// ---- device scratch ----
__device__ uint8_t g_cnt0[FRAMES*P0];
__device__ uint8_t g_lst0[FRAMES*P0*128];
__device__ float   g_w1r[9*C0*C1];                    // [tap][ci][co], x2 scaled
__device__ float   g_w2r[9*C1*C2];
__device__ float   g_w3r[9*C2*C3];
__device__ float   g_z1[(size_t)FRAMES*P1*C1];
__device__ uint8_t g_cnt1[FRAMES*P1];
__device__ uint8_t g_lst1[FRAMES*P1*64];
__device__ float   g_z2[(size_t)FRAMES*P2*C2];
__device__ uint8_t g_cnt2[FRAMES*P2];
__device__ uint8_t g_lst2[FRAMES*P2*32];
__device__ float   g_z3[(size_t)FRAMES*P3*C3];
__device__ int     g_cnt[3];
__device__ int     g_ticket;

#define ADD2(A, W) asm("add.rn.f32x2 %0, %0, %1;" : "+l"(A) : "l"(W))

// ---- merged prep (unchanged) ----
__global__ void k_prep(const float* __restrict__ x, const float* __restrict__ w1,
                       const float* __restrict__ w2, const float* __restrict__ w3) {
    if (blockIdx.x >= 256) {
        int idx = (blockIdx.x - 256)*256 + threadIdx.x;
        if (idx < 3) g_cnt[idx] = 0;
        if (idx == 3) g_ticket = 0;
        if (idx < 9*C0*C1) {
            int co = idx & 63;
            int ci = (idx >> 6) & 127;
            int tap = idx >> 13;
            g_w1r[idx] = 2.0f * w1[(ci*C1 + co)*9 + tap];
        } else if (idx < 9*C0*C1 + 9*C1*C2) {
            int i = idx - 9*C0*C1;
            int co = i & 31;
            int ci = (i >> 5) & 63;
            int tap = i >> 11;
            g_w2r[i] = 2.0f * w2[(ci*C2 + co)*9 + tap];
        } else if (idx < 9*C0*C1 + 9*C1*C2 + 9*C2*C3) {
            int i = idx - (9*C0*C1 + 9*C1*C2);
            int co = i & 1;
            int ci = (i >> 1) & 31;
            int tap = i >> 6;
            g_w3r[i] = 2.0f * w3[(ci*C3 + co)*9 + tap];
        }
        return;
    }
    const int lane = threadIdx.x & 31;
    const int gw = blockIdx.x*8 + (threadIdx.x >> 5);
    const int half = gw & 1;
    const int pp = gw >> 1;
    const int pix = pp % P0;
    const int n   = pp / P0;
    const uint32_t ltmask = (1u << lane) - 1u;
    uint32_t tmask[4];
    #pragma unroll
    for (int w = 0; w < 4; w++) {
        const float4* xp = (const float4*)(x + (((size_t)n*C0 + w*32 + lane)*P0 + pix)*TT)
                           + half*4;
        uint32_t m = 0;
        #pragma unroll
        for (int q = 0; q < 4; q++) {
            float4 vv = xp[q];
            m |= (vv.x >= 0.5f ? 1u : 0u) << (4*q);
            m |= (vv.y >= 0.5f ? 1u : 0u) << (4*q+1);
            m |= (vv.z >= 0.5f ? 1u : 0u) << (4*q+2);
            m |= (vv.w >= 0.5f ? 1u : 0u) << (4*q+3);
        }
        tmask[w] = m;
    }
    #pragma unroll 1
    for (int tt = 0; tt < 16; tt++) {
        const int t = half*16 + tt;
        const int p = (t*NB + n)*P0 + pix;
        uint8_t* lb = g_lst0 + p*128;
        int off = 0;
        #pragma unroll
        for (int w = 0; w < 4; w++) {
            bool s = (tmask[w] >> tt) & 1u;
            uint32_t bal = __ballot_sync(0xffffffffu, s);
            if (s) lb[off + __popc(bal & ltmask)] = (uint8_t)(w*32 + lane);
            off += __popc(bal);
        }
        if (lane == 0) g_cnt0[p] = (uint8_t)off;
    }
}

#define EV1(I) { u64 w_ = wb[(I)*32]; ADD2(acc, w_); }

// ==== layer 1 conv (unchanged, proven at floor) ====
template<int PH, int PW>
__device__ __forceinline__ void conv1body(float* sW, int firstBlk, int nblk) {
    constexpr int NKH = PH ? 2 : 1;
    constexpr int NKW = PW ? 2 : 1;
    constexpr int NT = NKH*NKW;
    for (int i = threadIdx.x; i < NT*C0*C1; i += 1024) {
        int ti = i >> 13;
        int r  = i & 8191;
        int kh = PH ? (ti/NKW)*2 : 1;
        int kw = PW ? (ti%NKW)*2 : 1;
        sW[i] = g_w1r[(kh*3+kw)*8192 + r];
    }
    __syncthreads();
    const int lane = threadIdx.x & 31;
    const int warp = threadIdx.x >> 5;
    constexpr int ROWS = PH ? H0-1 : H0;
    constexpr int COLS = PW ? W0-1 : W0;
    const int tasks = FRAMES*ROWS*COLS;
    for (int task = (blockIdx.x - firstBlk)*32 + warp; task < tasks; task += nblk*32) {
        const int ocol = task % COLS;
        const int tmp  = task / COLS;
        const int orow = tmp % ROWS;
        const int tn   = tmp / ROWS;
        const int fb   = tn*P0;
        int po[NT];
        #pragma unroll
        for (int a = 0; a < NKH; a++) {
            const int ih = PH ? (a == 0 ? orow+1 : orow) : orow;
            #pragma unroll
            for (int b = 0; b < NKW; b++) {
                const int iw = PW ? (b == 0 ? ocol+1 : ocol) : ocol;
                po[a*NKW+b] = fb + ih*W0 + iw;
            }
        }
        u64 acc = 0ull;
        #pragma unroll
        for (int ti = 0; ti < NT; ti++) {
            const int p = po[ti];
            const int c = g_cnt0[p];
            const uint8_t* lp = g_lst0 + p*128;
            const u64* wb = (const u64*)(sW + ti*8192) + lane;
            int j = 0;
            for (; j + 8 <= c; j += 8) {
                uint2 q = *(const uint2*)(lp + j);
                EV1((q.x      ) & 0xFF) EV1((q.x >>  8) & 0xFF)
                EV1((q.x >> 16) & 0xFF) EV1((q.x >> 24)       )
                EV1((q.y      ) & 0xFF) EV1((q.y >>  8) & 0xFF)
                EV1((q.y >> 16) & 0xFF) EV1((q.y >> 24)       )
            }
            if (j + 4 <= c) {
                uint32_t q = *(const uint32_t*)(lp + j);
                EV1((q      ) & 0xFF) EV1((q >>  8) & 0xFF)
                EV1((q >> 16) & 0xFF) EV1((q >> 24)       )
                j += 4;
            }
            for (; j < c; j++) EV1(lp[j]);
        }
        const int oh = PH ? 2*orow+1 : 2*orow;
        const int ow = PW ? 2*ocol+1 : 2*ocol;
        *(u64*)(g_z1 + ((size_t)tn*P1 + oh*W1 + ow)*C1 + 2*lane) = acc;
    }
}

__global__ void __launch_bounds__(1024)
k_conv1a() {
    extern __shared__ float sW[];
    const int blk = blockIdx.x;
    if (blk < 62)       conv1body<0,0>(sW, 0,   62);
    else if (blk < 179) conv1body<0,1>(sW, 62,  117);
    else                conv1body<1,0>(sW, 179, 117);
}
__global__ void __launch_bounds__(1024)
k_conv1b() {
    extern __shared__ float sW[];
    conv1body<1,1>(sW, 0, 148);
}

// ==== layer 2 conv: 4x4 output-block gather ====
// Inputs processed in DESCENDING (row,col): role r=0 -> input 2i+2, r=1 -> 2i+1, r=2 -> 2i.
// Row uses: r0:{(o3,kh0)}  r1:{(o1,kh0),(o2,kh1),(o3,kh2)}  r2:{(o0,kh1),(o1,kh2)}
// Tap offset T(kh,kw) = (kh*3+kw)*2048 floats. acc[or*4+oc].
#define X00(I) { const float* e_ = sWl + (I)*32; acc[15] += e_[0]; }
#define X01(I) { const float* e_ = sWl + (I)*32; acc[13] += e_[0]; acc[14] += e_[2048]; \
                 acc[15] += e_[4096]; }
#define X02(I) { const float* e_ = sWl + (I)*32; acc[12] += e_[2048]; acc[13] += e_[4096]; }
#define X10(I) { const float* e_ = sWl + (I)*32; acc[7] += e_[0]; acc[11] += e_[6144]; \
                 acc[15] += e_[12288]; }
#define X11(I) { const float* e_ = sWl + (I)*32; \
                 acc[5]  += e_[0];     acc[6]  += e_[2048];  acc[7]  += e_[4096]; \
                 acc[9]  += e_[6144];  acc[10] += e_[8192];  acc[11] += e_[10240]; \
                 acc[13] += e_[12288]; acc[14] += e_[14336]; acc[15] += e_[16384]; }
#define X12(I) { const float* e_ = sWl + (I)*32; \
                 acc[4]  += e_[2048];  acc[5]  += e_[4096]; \
                 acc[8]  += e_[8192];  acc[9]  += e_[10240]; \
                 acc[12] += e_[14336]; acc[13] += e_[16384]; }
#define X20(I) { const float* e_ = sWl + (I)*32; acc[3] += e_[6144]; acc[7] += e_[12288]; }
#define X21(I) { const float* e_ = sWl + (I)*32; \
                 acc[1]  += e_[6144];  acc[2]  += e_[8192];  acc[3]  += e_[10240]; \
                 acc[5]  += e_[12288]; acc[6]  += e_[14336]; acc[7]  += e_[16384]; }
#define X22(I) { const float* e_ = sWl + (I)*32; \
                 acc[0]  += e_[8192];  acc[1]  += e_[10240]; \
                 acc[4]  += e_[14336]; acc[5]  += e_[16384]; }
#define UE(I)  { acc0 += wb[(I)*32]; }

#define ELOOP2(P, U) { \
    const int c_ = g_cnt1[P]; \
    const uint8_t* lp_ = g_lst1 + (P)*64; \
    int j_ = 0; \
    for (; j_ + 4 <= c_; j_ += 4) { \
        uint32_t q_ = *(const uint32_t*)(lp_ + j_); \
        U((q_      ) & 0xFF) U((q_ >>  8) & 0xFF) \
        U((q_ >> 16) & 0xFF) U((q_ >> 24)       ) \
    } \
    for (; j_ < c_; j_++) U(lp_[j_]) \
}

__global__ void __launch_bounds__(1024)
k_conv2() {
    extern __shared__ float sW[];          // all 9 taps: [tap][ci][co] = 73728 B
    for (int i = threadIdx.x; i < 9*C1*C2; i += 1024) sW[i] = g_w2r[i];
    __syncthreads();
    const int lane = threadIdx.x & 31;
    const int warp = threadIdx.x >> 5;
    const float* sWl = sW + lane;
    const int BT  = FRAMES*15*15;          // 4x4 blocks cover outputs 0..59 x 0..59
    const int TOT = BT + FRAMES*121;       // edges: row 60 (61) + col 60 (60)
    for (int task = blockIdx.x*32 + warp; task < TOT; task += gridDim.x*32) {
        if (task < BT) {
            const int j  = task % 15;
            const int i  = (task/15) % 15;
            const int tn = task / 225;
            const int fb = tn*P1;
            const int br = 2*i + 2, bc = 2*j + 2;   // top input (descending from here)
            float acc[16];
            #pragma unroll
            for (int k = 0; k < 16; k++) acc[k] = 0.f;
            ELOOP2(fb + br*W1 + bc,       X00)
            ELOOP2(fb + br*W1 + bc-1,     X01)
            ELOOP2(fb + br*W1 + bc-2,     X02)
            ELOOP2(fb + (br-1)*W1 + bc,   X10)
            ELOOP2(fb + (br-1)*W1 + bc-1, X11)
            ELOOP2(fb + (br-1)*W1 + bc-2, X12)
            ELOOP2(fb + (br-2)*W1 + bc,   X20)
            ELOOP2(fb + (br-2)*W1 + bc-1, X21)
            ELOOP2(fb + (br-2)*W1 + bc-2, X22)
            const size_t zb = ((size_t)tn*P2 + (4*i)*W2 + 4*j)*C2 + lane;
            #pragma unroll
            for (int orow = 0; orow < 4; orow++)
                #pragma unroll
                for (int ocol = 0; ocol < 4; ocol++)
                    g_z2[zb + ((size_t)orow*W2 + ocol)*C2] = acc[orow*4 + ocol];
        } else {
            const int e  = task - BT;
            const int tn = e / 121;
            const int r  = e % 121;
            int oh, ow;
            if (r < 61) { oh = 60; ow = r; } else { oh = r - 61; ow = 60; }
            int khs[2], ihs[2], nh; int kws[2], iws[2], nw;
            if (oh & 1) { khs[0]=0; ihs[0]=(oh+1)>>1; khs[1]=2; ihs[1]=(oh-1)>>1; nh=2; }
            else        { khs[0]=1; ihs[0]=oh>>1; nh=1; }
            if (ow & 1) { kws[0]=0; iws[0]=(ow+1)>>1; kws[1]=2; iws[1]=(ow-1)>>1; nw=2; }
            else        { kws[0]=1; iws[0]=ow>>1; nw=1; }
            const int fb = tn*P1;
            float acc0 = 0.f;
            for (int a = 0; a < nh; a++)
                for (int b = 0; b < nw; b++) {
                    const int p = fb + ihs[a]*W1 + iws[b];
                    const float* wb = sW + (khs[a]*3 + kws[b])*2048 + lane;
                    ELOOP2(p, UE)
                }
            g_z2[((size_t)tn*P2 + oh*W2 + ow)*C2 + lane] = acc0;
        }
    }
}

// ---- LIF layer 1 (unchanged, pipelined) ----
__global__ void k_lif1() {
    const int gw = blockIdx.x*4 + (threadIdx.x >> 5);
    const int lane = threadIdx.x & 31;
    const int pix = gw % P1;
    const int n   = gw / P1;
    const uint32_t ltmask = (1u << lane) - 1u;
    const size_t a0 = ((size_t)n*P1 + pix)*C1 + 2*lane;
    const size_t st = (size_t)NB*P1*C1;
    float cur0=0.f, vol0=0.f, cur1=0.f, vol1=0.f;
    int cnt = 0;
    u64 buf[4];
    #pragma unroll
    for (int q = 0; q < 4; q++) buf[q] = *(const u64*)(g_z1 + a0 + (size_t)q*st);
    #pragma unroll
    for (int tb = 0; tb < 8; tb++) {
        u64 nxt[4];
        if (tb < 7) {
            #pragma unroll
            for (int q = 0; q < 4; q++)
                nxt[q] = *(const u64*)(g_z1 + a0 + (size_t)((tb+1)*4 + q)*st);
        }
        #pragma unroll
        for (int q = 0; q < 4; q++) {
            const int t = tb*4 + q;
            float2 zz = *(float2*)&buf[q];
            cur0 = 0.5f*cur0 + zz.x; vol0 = 0.5f*vol0 + cur0;
            cur1 = 0.5f*cur1 + zz.y; vol1 = 0.5f*vol1 + cur1;
            bool s0 = (vol0 >= 1.0f); vol0 = s0 ? 0.f : vol0;
            bool s1 = (vol1 >= 1.0f); vol1 = s1 ? 0.f : vol1;
            cnt += (s0 ? 1 : 0) + (s1 ? 1 : 0);
            uint32_t b0 = __ballot_sync(0xffffffffu, s0);
            uint32_t b1 = __ballot_sync(0xffffffffu, s1);
            const int p = (t*NB + n)*P1 + pix;
            const int off0 = __popc(b0 & ltmask) + __popc(b1 & ltmask);
            if (s0) g_lst1[p*64 + off0] = (uint8_t)(2*lane);
            if (s1) g_lst1[p*64 + off0 + (s0 ? 1 : 0)] = (uint8_t)(2*lane + 1);
            if (lane == 0) g_cnt1[p] = (uint8_t)(__popc(b0) + __popc(b1));
        }
        if (tb < 7) {
            #pragma unroll
            for (int q = 0; q < 4; q++) buf[q] = nxt[q];
        }
    }
    cnt = __reduce_add_sync(0xffffffffu, cnt);
    if (lane == 0) atomicAdd(&g_cnt[0], cnt);
}

// ---- LIF layer 2 (unchanged, pipelined, two pixels per warp) ----
__global__ void k_lif2() {
    const int gw = blockIdx.x*(blockDim.x >> 5) + (threadIdx.x >> 5);
    const int lane = threadIdx.x & 31;
    const int half = lane >> 4;
    const int j    = lane & 15;
    const int pix2 = gw*2 + half;
    if (pix2 >= NB*P2) return;
    const int pix = pix2 % P2;
    const int n   = pix2 / P2;
    const uint32_t hmask  = half ? 0xFFFF0000u : 0x0000FFFFu;
    const uint32_t ltmask = ((1u << lane) - 1u) & hmask;
    const size_t a0 = ((size_t)n*P2 + pix)*C2 + 2*j;
    const size_t st = (size_t)NB*P2*C2;
    float cur0=0.f, vol0=0.f, cur1=0.f, vol1=0.f;
    int cnt = 0;
    u64 buf[4];
    #pragma unroll
    for (int q = 0; q < 4; q++) buf[q] = *(const u64*)(g_z2 + a0 + (size_t)q*st);
    #pragma unroll
    for (int tb = 0; tb < 8; tb++) {
        u64 nxt[4];
        if (tb < 7) {
            #pragma unroll
            for (int q = 0; q < 4; q++)
                nxt[q] = *(const u64*)(g_z2 + a0 + (size_t)((tb+1)*4 + q)*st);
        }
        #pragma unroll
        for (int q = 0; q < 4; q++) {
            const int t = tb*4 + q;
            float2 zz = *(float2*)&buf[q];
            cur0 = 0.5f*cur0 + zz.x; vol0 = 0.5f*vol0 + cur0;
            cur1 = 0.5f*cur1 + zz.y; vol1 = 0.5f*vol1 + cur1;
            bool s0 = (vol0 >= 1.0f); vol0 = s0 ? 0.f : vol0;
            bool s1 = (vol1 >= 1.0f); vol1 = s1 ? 0.f : vol1;
            cnt += (s0 ? 1 : 0) + (s1 ? 1 : 0);
            uint32_t b0 = __ballot_sync(0xffffffffu, s0) & hmask;
            uint32_t b1 = __ballot_sync(0xffffffffu, s1) & hmask;
            const int p = (t*NB + n)*P2 + pix;
            const int off0 = __popc(b0 & ltmask) + __popc(b1 & ltmask);
            if (s0) g_lst2[p*32 + off0] = (uint8_t)(2*j);
            if (s1) g_lst2[p*32 + off0 + (s0 ? 1 : 0)] = (uint8_t)(2*j + 1);
            if (j == 0) g_cnt2[p] = (uint8_t)(__popc(b0) + __popc(b1));
        }
        if (tb < 7) {
            #pragma unroll
            for (int q = 0; q < 4; q++) buf[q] = nxt[q];
        }
    }
    cnt = __reduce_add_sync(0xffffffffu, cnt);
    if (lane == 0) atomicAdd(&g_cnt[1], cnt);
}

// ==== layer 3 conv: 4x4 output-block gather, thread per block ====
// Same role structure; tap offset T3(kh,kw) = (kh*3+kw)*32 u64 entries.
#define Y00(I) { ADD2(a[15], sW64[      (I)]); }
#define Y01(I) { ADD2(a[13], sW64[      (I)]); ADD2(a[14], sW64[ 32 + (I)]); \
                 ADD2(a[15], sW64[ 64 + (I)]); }
#define Y02(I) { ADD2(a[12], sW64[ 32 + (I)]); ADD2(a[13], sW64[ 64 + (I)]); }
#define Y10(I) { ADD2(a[7],  sW64[      (I)]); ADD2(a[11], sW64[ 96 + (I)]); \
                 ADD2(a[15], sW64[192 + (I)]); }
#define Y11(I) { ADD2(a[5],  sW64[      (I)]); ADD2(a[6],  sW64[ 32 + (I)]); \
                 ADD2(a[7],  sW64[ 64 + (I)]); ADD2(a[9],  sW64[ 96 + (I)]); \
                 ADD2(a[10], sW64[128 + (I)]); ADD2(a[11], sW64[160 + (I)]); \
                 ADD2(a[13], sW64[192 + (I)]); ADD2(a[14], sW64[224 + (I)]); \
                 ADD2(a[15], sW64[256 + (I)]); }
#define Y12(I) { ADD2(a[4],  sW64[ 32 + (I)]); ADD2(a[5],  sW64[ 64 + (I)]); \
                 ADD2(a[8],  sW64[128 + (I)]); ADD2(a[9],  sW64[160 + (I)]); \
                 ADD2(a[12], sW64[224 + (I)]); ADD2(a[13], sW64[256 + (I)]); }
#define Y20(I) { ADD2(a[3],  sW64[ 96 + (I)]); ADD2(a[7],  sW64[192 + (I)]); }
#define Y21(I) { ADD2(a[1],  sW64[ 96 + (I)]); ADD2(a[2],  sW64[128 + (I)]); \
                 ADD2(a[3],  sW64[160 + (I)]); ADD2(a[5],  sW64[192 + (I)]); \
                 ADD2(a[6],  sW64[224 + (I)]); ADD2(a[7],  sW64[256 + (I)]); }
#define Y22(I) { ADD2(a[0],  sW64[128 + (I)]); ADD2(a[1],  sW64[160 + (I)]); \
                 ADD2(a[4],  sW64[224 + (I)]); ADD2(a[5],  sW64[256 + (I)]); }
#define VE(I)  { u64 w_ = wb[(I)]; ADD2(acc, w_); }

#define ELOOP3(P, U) { \
    const int c_ = g_cnt2[P]; \
    const uint8_t* lp_ = g_lst2 + (P)*32; \
    int j_ = 0; \
    for (; j_ + 4 <= c_; j_ += 4) { \
        uint32_t q_ = *(const uint32_t*)(lp_ + j_); \
        U((q_      ) & 0xFF) U((q_ >>  8) & 0xFF) \
        U((q_ >> 16) & 0xFF) U((q_ >> 24)       ) \
    } \
    for (; j_ < c_; j_++) U(lp_[j_]) \
}

__global__ void k_conv3() {
    __shared__ u64 sW64[9*C2];
    for (int i = threadIdx.x; i < 9*C2*2; i += blockDim.x)
        ((float*)sW64)[i] = g_w3r[i];
    __syncthreads();
    const int task = blockIdx.x*blockDim.x + threadIdx.x;
    const int BT  = FRAMES*30*30;          // 4x4 blocks cover outputs 0..119 sq
    const int TOT = BT + FRAMES*241;       // edges: row 120 (121) + col 120 (120)
    if (task >= TOT) return;
    if (task < BT) {
        const int j  = task % 30;
        const int i  = (task/30) % 30;
        const int tn = task / 900;
        const int fb = tn*P2;
        const int br = 2*i + 2, bc = 2*j + 2;
        u64 a[16];
        #pragma unroll
        for (int k = 0; k < 16; k++) a[k] = 0ull;
        ELOOP3(fb + br*W2 + bc,       Y00)
        ELOOP3(fb + br*W2 + bc-1,     Y01)
        ELOOP3(fb + br*W2 + bc-2,     Y02)
        ELOOP3(fb + (br-1)*W2 + bc,   Y10)
        ELOOP3(fb + (br-1)*W2 + bc-1, Y11)
        ELOOP3(fb + (br-1)*W2 + bc-2, Y12)
        ELOOP3(fb + (br-2)*W2 + bc,   Y20)
        ELOOP3(fb + (br-2)*W2 + bc-1, Y21)
        ELOOP3(fb + (br-2)*W2 + bc-2, Y22)
        const size_t zb = ((size_t)tn*P3 + (4*i)*W3 + 4*j)*2;
        #pragma unroll
        for (int orow = 0; orow < 4; orow++)
            #pragma unroll
            for (int ocol = 0; ocol < 4; ocol++)
                *(u64*)(g_z3 + zb + ((size_t)orow*W3 + ocol)*2) = a[orow*4 + ocol];
    } else {
        const int e  = task - BT;
        const int tn = e / 241;
        const int r  = e % 241;
        int oh, ow;
        if (r < 121) { oh = 120; ow = r; } else { oh = r - 121; ow = 120; }
        int khs[2], ihs[2], nh; int kws[2], iws[2], nw;
        if (oh & 1) { khs[0]=0; ihs[0]=(oh+1)>>1; khs[1]=2; ihs[1]=(oh-1)>>1; nh=2; }
        else        { khs[0]=1; ihs[0]=oh>>1; nh=1; }
        if (ow & 1) { kws[0]=0; iws[0]=(ow+1)>>1; kws[1]=2; iws[1]=(ow-1)>>1; nw=2; }
        else        { kws[0]=1; iws[0]=ow>>1; nw=1; }
        u64 acc = 0ull;
        for (int aa = 0; aa < nh; aa++)
            for (int b = 0; b < nw; b++) {
                const int p = tn*P2 + ihs[aa]*W2 + iws[b];
                const u64* wb = sW64 + (khs[aa]*3 + kws[b])*C2;
                ELOOP3(p, VE)
            }
        *(u64*)(g_z3 + ((size_t)tn*P3 + oh*W3 + ow)*2) = acc;
    }
}

// ---- final LIF (unchanged): pipelined, bitpacked, ticket-based means ----
__global__ void k_lif3out(float* __restrict__ out, int off) {
    const int idx = blockIdx.x*blockDim.x + threadIdx.x;
    const bool valid = (idx < NB*P3);
    int cnt = 0;
    if (valid) {
        const int pix = idx % P3;
        const int n   = idx / P3;
        const size_t a0 = ((size_t)n*P3 + pix)*C3;
        const size_t st = (size_t)NB*P3*C3;
        float cur0=0.f, vol0=0.f, cur1=0.f, vol1=0.f;
        uint32_t bits0 = 0, bits1 = 0;
        u64 buf[4];
        #pragma unroll
        for (int q = 0; q < 4; q++) buf[q] = *(const u64*)(g_z3 + a0 + (size_t)q*st);
        #pragma unroll
        for (int tb = 0; tb < 8; tb++) {
            u64 nxt[4];
            if (tb < 7) {
                #pragma unroll
                for (int q = 0; q < 4; q++)
                    nxt[q] = *(const u64*)(g_z3 + a0 + (size_t)((tb+1)*4 + q)*st);
            }
            #pragma unroll
            for (int q = 0; q < 4; q++) {
                const int t = tb*4 + q;
                float2 zv = *(float2*)&buf[q];
                cur0 = 0.5f*cur0 + zv.x; vol0 = 0.5f*vol0 + cur0;
                cur1 = 0.5f*cur1 + zv.y; vol1 = 0.5f*vol1 + cur1;
                bool s0 = (vol0 >= 1.0f), s1 = (vol1 >= 1.0f);
                vol0 = s0 ? 0.f : vol0;  vol1 = s1 ? 0.f : vol1;
                bits0 |= (s0 ? 1u : 0u) << t;
                bits1 |= (s1 ? 1u : 0u) << t;
            }
            if (tb < 7) {
                #pragma unroll
                for (int q = 0; q < 4; q++) buf[q] = nxt[q];
            }
        }
        cnt = __popc(bits0) + __popc(bits1);
        float4* op0 = (float4*)(out + (((size_t)n*C3 + 0)*P3 + pix)*TT);
        float4* op1 = (float4*)(out + (((size_t)n*C3 + 1)*P3 + pix)*TT);
        #pragma unroll
        for (int q = 0; q < 8; q++) {
            op0[q] = make_float4((float)((bits0 >> (4*q  )) & 1u),
                                 (float)((bits0 >> (4*q+1)) & 1u),
                                 (float)((bits0 >> (4*q+2)) & 1u),
                                 (float)((bits0 >> (4*q+3)) & 1u));
            op1[q] = make_float4((float)((bits1 >> (4*q  )) & 1u),
                                 (float)((bits1 >> (4*q+1)) & 1u),
                                 (float)((bits1 >> (4*q+2)) & 1u),
                                 (float)((bits1 >> (4*q+3)) & 1u));
        }
    }
    cnt = __reduce_add_sync(0xffffffffu, cnt);
    if ((threadIdx.x & 31) == 0 && cnt) atomicAdd(&g_cnt[2], cnt);
    __syncthreads();
    if (threadIdx.x == 0) {
        __threadfence();
        int tk = atomicAdd(&g_ticket, 1);
        if (tk == gridDim.x - 1) {
            out[off+0] = (float)g_cnt[0] * (1.0f / (float)((size_t)NB*C1*P1*TT));
            out[off+1] = (float)g_cnt[1] * (1.0f / (float)((size_t)NB*C2*P2*TT));
            out[off+2] = (float)g_cnt[2] * (1.0f / (float)((size_t)NB*C3*P3*TT));
        }
    }
}

extern "C" void kernel_launch(void* const* d_in, const int* in_sizes, int n_in,
                              void* d_out, int out_size) {
    const float* x  = (const float*)d_in[0];
    const float* w1 = (const float*)d_in[1];
    const float* w2 = (const float*)d_in[2];
    const float* w3 = (const float*)d_in[3];
    float* out = (float*)d_out;

    const int smem1a = 2*C0*C1*4;   // 65536
    const int smem1b = 4*C0*C1*4;   // 131072
    const int smem2  = 9*C1*C2*4;   // 73728
    cudaFuncSetAttribute((const void*)k_conv1a,
                         cudaFuncAttributeMaxDynamicSharedMemorySize, smem1a);
    cudaFuncSetAttribute((const void*)k_conv1b,
                         cudaFuncAttributeMaxDynamicSharedMemorySize, smem1b);
    cudaFuncSetAttribute((const void*)k_conv2,
                         cudaFuncAttributeMaxDynamicSharedMemorySize, smem2);

    const int wtot = 9*C0*C1 + 9*C1*C2 + 9*C2*C3;
    k_prep<<<256 + (wtot + 255)/256, 256>>>(x, w1, w2, w3);
    k_conv1a<<<296, 1024, smem1a>>>();
    k_conv1b<<<148, 1024, smem1b>>>();
    k_lif1<<<961, 128>>>();
    k_conv2<<<296, 1024, smem2>>>();
    k_lif2<<<(NB*P2/2 + 7)/8, 256>>>();
    k_conv3<<<(FRAMES*(30*30 + 241) + 255)/256, 256>>>();
    k_lif3out<<<(NB*P3 + 255)/256, 256>>>(out, out_size - 3);
}

// round 15
// speedup vs baseline: 1.0222x; 1.0222x over previous
#include <cuda_runtime.h>
#include <stdint.h>

#define TT 32
#define NB 4
#define FRAMES (TT*NB)

#define C0 128
#define H0 16
#define W0 16
#define C1 64
#define H1 31
#define W1 31
#define C2 32
#define H2 61
#define W2 61
#define C3 2
#define H3 121
#define W3 121

#define P0 (H0*W0)     // 256
#define P1 (H1*W1)     // 961
#define P2 (H2*W2)     // 3721
#define P3 (H3*W3)     // 14641

typedef unsigned long long u64;

// ---- device scratch ----
__device__ uint8_t g_cnt0[FRAMES*P0];
__device__ uint8_t g_lst0[FRAMES*P0*128];
__device__ float   g_w1r[9*C0*C1];                    // [tap][ci][co], x2 scaled
__device__ float   g_w2r[9*C1*C2];
__device__ float   g_w3r[9*C2*C3];
__device__ float   g_z1[(size_t)FRAMES*P1*C1];
__device__ uint8_t g_cnt1[FRAMES*P1];
__device__ uint8_t g_lst1[FRAMES*P1*64];
__device__ float   g_z2[(size_t)FRAMES*P2*C2];
__device__ uint8_t g_cnt2[FRAMES*P2];
__device__ uint8_t g_lst2[FRAMES*P2*32];
__device__ float   g_z3[(size_t)FRAMES*P3*C3];
__device__ int     g_cnt[3];
__device__ int     g_ticket;

#define ADD2(A, W) asm("add.rn.f32x2 %0, %0, %1;" : "+l"(A) : "l"(W))
#define GRID_SYNC() cudaGridDependencySynchronize()

// ---- merged prep (first kernel: no PDL sync) ----
__global__ void k_prep(const float* __restrict__ x, const float* __restrict__ w1,
                       const float* __restrict__ w2, const float* __restrict__ w3) {
    if (blockIdx.x >= 256) {
        int idx = (blockIdx.x - 256)*256 + threadIdx.x;
        if (idx < 3) g_cnt[idx] = 0;
        if (idx == 3) g_ticket = 0;
        if (idx < 9*C0*C1) {
            int co = idx & 63;
            int ci = (idx >> 6) & 127;
            int tap = idx >> 13;
            g_w1r[idx] = 2.0f * w1[(ci*C1 + co)*9 + tap];
        } else if (idx < 9*C0*C1 + 9*C1*C2) {
            int i = idx - 9*C0*C1;
            int co = i & 31;
            int ci = (i >> 5) & 63;
            int tap = i >> 11;
            g_w2r[i] = 2.0f * w2[(ci*C2 + co)*9 + tap];
        } else if (idx < 9*C0*C1 + 9*C1*C2 + 9*C2*C3) {
            int i = idx - (9*C0*C1 + 9*C1*C2);
            int co = i & 1;
            int ci = (i >> 1) & 31;
            int tap = i >> 6;
            g_w3r[i] = 2.0f * w3[(ci*C3 + co)*9 + tap];
        }
        return;
    }
    const int lane = threadIdx.x & 31;
    const int gw = blockIdx.x*8 + (threadIdx.x >> 5);
    const int half = gw & 1;
    const int pp = gw >> 1;
    const int pix = pp % P0;
    const int n   = pp / P0;
    const uint32_t ltmask = (1u << lane) - 1u;
    uint32_t tmask[4];
    #pragma unroll
    for (int w = 0; w < 4; w++) {
        const float4* xp = (const float4*)(x + (((size_t)n*C0 + w*32 + lane)*P0 + pix)*TT)
                           + half*4;
        uint32_t m = 0;
        #pragma unroll
        for (int q = 0; q < 4; q++) {
            float4 vv = xp[q];
            m |= (vv.x >= 0.5f ? 1u : 0u) << (4*q);
            m |= (vv.y >= 0.5f ? 1u : 0u) << (4*q+1);
            m |= (vv.z >= 0.5f ? 1u : 0u) << (4*q+2);
            m |= (vv.w >= 0.5f ? 1u : 0u) << (4*q+3);
        }
        tmask[w] = m;
    }
    #pragma unroll 1
    for (int tt = 0; tt < 16; tt++) {
        const int t = half*16 + tt;
        const int p = (t*NB + n)*P0 + pix;
        uint8_t* lb = g_lst0 + p*128;
        int off = 0;
        #pragma unroll
        for (int w = 0; w < 4; w++) {
            bool s = (tmask[w] >> tt) & 1u;
            uint32_t bal = __ballot_sync(0xffffffffu, s);
            if (s) lb[off + __popc(bal & ltmask)] = (uint8_t)(w*32 + lane);
            off += __popc(bal);
        }
        if (lane == 0) g_cnt0[p] = (uint8_t)off;
    }
}

#define EV1(I) { u64 w_ = wb[(I)*32]; ADD2(acc, w_); }

// ==== layer 1 conv (bodies unchanged; grid-sync at entry) ====
template<int PH, int PW>
__device__ __forceinline__ void conv1body(float* sW, int firstBlk, int nblk) {
    constexpr int NKH = PH ? 2 : 1;
    constexpr int NKW = PW ? 2 : 1;
    constexpr int NT = NKH*NKW;
    for (int i = threadIdx.x; i < NT*C0*C1; i += 1024) {
        int ti = i >> 13;
        int r  = i & 8191;
        int kh = PH ? (ti/NKW)*2 : 1;
        int kw = PW ? (ti%NKW)*2 : 1;
        sW[i] = g_w1r[(kh*3+kw)*8192 + r];
    }
    __syncthreads();
    const int lane = threadIdx.x & 31;
    const int warp = threadIdx.x >> 5;
    constexpr int ROWS = PH ? H0-1 : H0;
    constexpr int COLS = PW ? W0-1 : W0;
    const int tasks = FRAMES*ROWS*COLS;
    for (int task = (blockIdx.x - firstBlk)*32 + warp; task < tasks; task += nblk*32) {
        const int ocol = task % COLS;
        const int tmp  = task / COLS;
        const int orow = tmp % ROWS;
        const int tn   = tmp / ROWS;
        const int fb   = tn*P0;
        int po[NT];
        #pragma unroll
        for (int a = 0; a < NKH; a++) {
            const int ih = PH ? (a == 0 ? orow+1 : orow) : orow;
            #pragma unroll
            for (int b = 0; b < NKW; b++) {
                const int iw = PW ? (b == 0 ? ocol+1 : ocol) : ocol;
                po[a*NKW+b] = fb + ih*W0 + iw;
            }
        }
        u64 acc = 0ull;
        #pragma unroll
        for (int ti = 0; ti < NT; ti++) {
            const int p = po[ti];
            const int c = g_cnt0[p];
            const uint8_t* lp = g_lst0 + p*128;
            const u64* wb = (const u64*)(sW + ti*8192) + lane;
            int j = 0;
            for (; j + 8 <= c; j += 8) {
                uint2 q = *(const uint2*)(lp + j);
                EV1((q.x      ) & 0xFF) EV1((q.x >>  8) & 0xFF)
                EV1((q.x >> 16) & 0xFF) EV1((q.x >> 24)       )
                EV1((q.y      ) & 0xFF) EV1((q.y >>  8) & 0xFF)
                EV1((q.y >> 16) & 0xFF) EV1((q.y >> 24)       )
            }
            if (j + 4 <= c) {
                uint32_t q = *(const uint32_t*)(lp + j);
                EV1((q      ) & 0xFF) EV1((q >>  8) & 0xFF)
                EV1((q >> 16) & 0xFF) EV1((q >> 24)       )
                j += 4;
            }
            for (; j < c; j++) EV1(lp[j]);
        }
        const int oh = PH ? 2*orow+1 : 2*orow;
        const int ow = PW ? 2*ocol+1 : 2*ocol;
        *(u64*)(g_z1 + ((size_t)tn*P1 + oh*W1 + ow)*C1 + 2*lane) = acc;
    }
}

__global__ void __launch_bounds__(1024)
k_conv1a() {
    GRID_SYNC();
    extern __shared__ float sW[];
    const int blk = blockIdx.x;
    if (blk < 62)       conv1body<0,0>(sW, 0,   62);
    else if (blk < 179) conv1body<0,1>(sW, 62,  117);
    else                conv1body<1,0>(sW, 179, 117);
}
__global__ void __launch_bounds__(1024)
k_conv1b() {
    GRID_SYNC();
    extern __shared__ float sW[];
    conv1body<1,1>(sW, 0, 148);
}

// ==== layer 2 conv: 4x4 output-block gather (unchanged body) ====
#define X00(I) { const float* e_ = sWl + (I)*32; acc[15] += e_[0]; }
#define X01(I) { const float* e_ = sWl + (I)*32; acc[13] += e_[0]; acc[14] += e_[2048]; \
                 acc[15] += e_[4096]; }
#define X02(I) { const float* e_ = sWl + (I)*32; acc[12] += e_[2048]; acc[13] += e_[4096]; }
#define X10(I) { const float* e_ = sWl + (I)*32; acc[7] += e_[0]; acc[11] += e_[6144]; \
                 acc[15] += e_[12288]; }
#define X11(I) { const float* e_ = sWl + (I)*32; \
                 acc[5]  += e_[0];     acc[6]  += e_[2048];  acc[7]  += e_[4096]; \
                 acc[9]  += e_[6144];  acc[10] += e_[8192];  acc[11] += e_[10240]; \
                 acc[13] += e_[12288]; acc[14] += e_[14336]; acc[15] += e_[16384]; }
#define X12(I) { const float* e_ = sWl + (I)*32; \
                 acc[4]  += e_[2048];  acc[5]  += e_[4096]; \
                 acc[8]  += e_[8192];  acc[9]  += e_[10240]; \
                 acc[12] += e_[14336]; acc[13] += e_[16384]; }
#define X20(I) { const float* e_ = sWl + (I)*32; acc[3] += e_[6144]; acc[7] += e_[12288]; }
#define X21(I) { const float* e_ = sWl + (I)*32; \
                 acc[1]  += e_[6144];  acc[2]  += e_[8192];  acc[3]  += e_[10240]; \
                 acc[5]  += e_[12288]; acc[6]  += e_[14336]; acc[7]  += e_[16384]; }
#define X22(I) { const float* e_ = sWl + (I)*32; \
                 acc[0]  += e_[8192];  acc[1]  += e_[10240]; \
                 acc[4]  += e_[14336]; acc[5]  += e_[16384]; }
#define UE(I)  { acc0 += wb[(I)*32]; }

#define ELOOP2(P, U) { \
    const int c_ = g_cnt1[P]; \
    const uint8_t* lp_ = g_lst1 + (P)*64; \
    int j_ = 0; \
    for (; j_ + 4 <= c_; j_ += 4) { \
        uint32_t q_ = *(const uint32_t*)(lp_ + j_); \
        U((q_      ) & 0xFF) U((q_ >>  8) & 0xFF) \
        U((q_ >> 16) & 0xFF) U((q_ >> 24)       ) \
    } \
    for (; j_ < c_; j_++) U(lp_[j_]) \
}

__global__ void __launch_bounds__(1024)
k_conv2() {
    GRID_SYNC();
    extern __shared__ float sW[];
    for (int i = threadIdx.x; i < 9*C1*C2; i += 1024) sW[i] = g_w2r[i];
    __syncthreads();
    const int lane = threadIdx.x & 31;
    const int warp = threadIdx.x >> 5;
    const float* sWl = sW + lane;
    const int BT  = FRAMES*15*15;
    const int TOT = BT + FRAMES*121;
    for (int task = blockIdx.x*32 + warp; task < TOT; task += gridDim.x*32) {
        if (task < BT) {
            const int j  = task % 15;
            const int i  = (task/15) % 15;
            const int tn = task / 225;
            const int fb = tn*P1;
            const int br = 2*i + 2, bc = 2*j + 2;
            float acc[16];
            #pragma unroll
            for (int k = 0; k < 16; k++) acc[k] = 0.f;
            ELOOP2(fb + br*W1 + bc,       X00)
            ELOOP2(fb + br*W1 + bc-1,     X01)
            ELOOP2(fb + br*W1 + bc-2,     X02)
            ELOOP2(fb + (br-1)*W1 + bc,   X10)
            ELOOP2(fb + (br-1)*W1 + bc-1, X11)
            ELOOP2(fb + (br-1)*W1 + bc-2, X12)
            ELOOP2(fb + (br-2)*W1 + bc,   X20)
            ELOOP2(fb + (br-2)*W1 + bc-1, X21)
            ELOOP2(fb + (br-2)*W1 + bc-2, X22)
            const size_t zb = ((size_t)tn*P2 + (4*i)*W2 + 4*j)*C2 + lane;
            #pragma unroll
            for (int orow = 0; orow < 4; orow++)
                #pragma unroll
                for (int ocol = 0; ocol < 4; ocol++)
                    g_z2[zb + ((size_t)orow*W2 + ocol)*C2] = acc[orow*4 + ocol];
        } else {
            const int e  = task - BT;
            const int tn = e / 121;
            const int r  = e % 121;
            int oh, ow;
            if (r < 61) { oh = 60; ow = r; } else { oh = r - 61; ow = 60; }
            int khs[2], ihs[2], nh; int kws[2], iws[2], nw;
            if (oh & 1) { khs[0]=0; ihs[0]=(oh+1)>>1; khs[1]=2; ihs[1]=(oh-1)>>1; nh=2; }
            else        { khs[0]=1; ihs[0]=oh>>1; nh=1; }
            if (ow & 1) { kws[0]=0; iws[0]=(ow+1)>>1; kws[1]=2; iws[1]=(ow-1)>>1; nw=2; }
            else        { kws[0]=1; iws[0]=ow>>1; nw=1; }
            const int fb = tn*P1;
            float acc0 = 0.f;
            for (int a = 0; a < nh; a++)
                for (int b = 0; b < nw; b++) {
                    const int p = fb + ihs[a]*W1 + iws[b];
                    const float* wb = sW + (khs[a]*3 + kws[b])*2048 + lane;
                    ELOOP2(p, UE)
                }
            g_z2[((size_t)tn*P2 + oh*W2 + ow)*C2 + lane] = acc0;
        }
    }
}

// ---- LIF layer 1 (unchanged body) ----
__global__ void k_lif1() {
    GRID_SYNC();
    const int gw = blockIdx.x*4 + (threadIdx.x >> 5);
    const int lane = threadIdx.x & 31;
    const int pix = gw % P1;
    const int n   = gw / P1;
    const uint32_t ltmask = (1u << lane) - 1u;
    const size_t a0 = ((size_t)n*P1 + pix)*C1 + 2*lane;
    const size_t st = (size_t)NB*P1*C1;
    float cur0=0.f, vol0=0.f, cur1=0.f, vol1=0.f;
    int cnt = 0;
    u64 buf[4];
    #pragma unroll
    for (int q = 0; q < 4; q++) buf[q] = *(const u64*)(g_z1 + a0 + (size_t)q*st);
    #pragma unroll
    for (int tb = 0; tb < 8; tb++) {
        u64 nxt[4];
        if (tb < 7) {
            #pragma unroll
            for (int q = 0; q < 4; q++)
                nxt[q] = *(const u64*)(g_z1 + a0 + (size_t)((tb+1)*4 + q)*st);
        }
        #pragma unroll
        for (int q = 0; q < 4; q++) {
            const int t = tb*4 + q;
            float2 zz = *(float2*)&buf[q];
            cur0 = 0.5f*cur0 + zz.x; vol0 = 0.5f*vol0 + cur0;
            cur1 = 0.5f*cur1 + zz.y; vol1 = 0.5f*vol1 + cur1;
            bool s0 = (vol0 >= 1.0f); vol0 = s0 ? 0.f : vol0;
            bool s1 = (vol1 >= 1.0f); vol1 = s1 ? 0.f : vol1;
            cnt += (s0 ? 1 : 0) + (s1 ? 1 : 0);
            uint32_t b0 = __ballot_sync(0xffffffffu, s0);
            uint32_t b1 = __ballot_sync(0xffffffffu, s1);
            const int p = (t*NB + n)*P1 + pix;
            const int off0 = __popc(b0 & ltmask) + __popc(b1 & ltmask);
            if (s0) g_lst1[p*64 + off0] = (uint8_t)(2*lane);
            if (s1) g_lst1[p*64 + off0 + (s0 ? 1 : 0)] = (uint8_t)(2*lane + 1);
            if (lane == 0) g_cnt1[p] = (uint8_t)(__popc(b0) + __popc(b1));
        }
        if (tb < 7) {
            #pragma unroll
            for (int q = 0; q < 4; q++) buf[q] = nxt[q];
        }
    }
    cnt = __reduce_add_sync(0xffffffffu, cnt);
    if (lane == 0) atomicAdd(&g_cnt[0], cnt);
}

// ---- LIF layer 2 (unchanged body) ----
__global__ void k_lif2() {
    GRID_SYNC();
    const int gw = blockIdx.x*(blockDim.x >> 5) + (threadIdx.x >> 5);
    const int lane = threadIdx.x & 31;
    const int half = lane >> 4;
    const int j    = lane & 15;
    const int pix2 = gw*2 + half;
    if (pix2 >= NB*P2) return;
    const int pix = pix2 % P2;
    const int n   = pix2 / P2;
    const uint32_t hmask  = half ? 0xFFFF0000u : 0x0000FFFFu;
    const uint32_t ltmask = ((1u << lane) - 1u) & hmask;
    const size_t a0 = ((size_t)n*P2 + pix)*C2 + 2*j;
    const size_t st = (size_t)NB*P2*C2;
    float cur0=0.f, vol0=0.f, cur1=0.f, vol1=0.f;
    int cnt = 0;
    u64 buf[4];
    #pragma unroll
    for (int q = 0; q < 4; q++) buf[q] = *(const u64*)(g_z2 + a0 + (size_t)q*st);
    #pragma unroll
    for (int tb = 0; tb < 8; tb++) {
        u64 nxt[4];
        if (tb < 7) {
            #pragma unroll
            for (int q = 0; q < 4; q++)
                nxt[q] = *(const u64*)(g_z2 + a0 + (size_t)((tb+1)*4 + q)*st);
        }
        #pragma unroll
        for (int q = 0; q < 4; q++) {
            const int t = tb*4 + q;
            float2 zz = *(float2*)&buf[q];
            cur0 = 0.5f*cur0 + zz.x; vol0 = 0.5f*vol0 + cur0;
            cur1 = 0.5f*cur1 + zz.y; vol1 = 0.5f*vol1 + cur1;
            bool s0 = (vol0 >= 1.0f); vol0 = s0 ? 0.f : vol0;
            bool s1 = (vol1 >= 1.0f); vol1 = s1 ? 0.f : vol1;
            cnt += (s0 ? 1 : 0) + (s1 ? 1 : 0);
            uint32_t b0 = __ballot_sync(0xffffffffu, s0) & hmask;
            uint32_t b1 = __ballot_sync(0xffffffffu, s1) & hmask;
            const int p = (t*NB + n)*P2 + pix;
            const int off0 = __popc(b0 & ltmask) + __popc(b1 & ltmask);
            if (s0) g_lst2[p*32 + off0] = (uint8_t)(2*j);
            if (s1) g_lst2[p*32 + off0 + (s0 ? 1 : 0)] = (uint8_t)(2*j + 1);
            if (j == 0) g_cnt2[p] = (uint8_t)(__popc(b0) + __popc(b1));
        }
        if (tb < 7) {
            #pragma unroll
            for (int q = 0; q < 4; q++) buf[q] = nxt[q];
        }
    }
    cnt = __reduce_add_sync(0xffffffffu, cnt);
    if (lane == 0) atomicAdd(&g_cnt[1], cnt);
}

// ==== layer 3 conv: 4x4 output-block gather (unchanged body) ====
#define Y00(I) { ADD2(a[15], sW64[      (I)]); }
#define Y01(I) { ADD2(a[13], sW64[      (I)]); ADD2(a[14], sW64[ 32 + (I)]); \
                 ADD2(a[15], sW64[ 64 + (I)]); }
#define Y02(I) { ADD2(a[12], sW64[ 32 + (I)]); ADD2(a[13], sW64[ 64 + (I)]); }
#define Y10(I) { ADD2(a[7],  sW64[      (I)]); ADD2(a[11], sW64[ 96 + (I)]); \
                 ADD2(a[15], sW64[192 + (I)]); }
#define Y11(I) { ADD2(a[5],  sW64[      (I)]); ADD2(a[6],  sW64[ 32 + (I)]); \
                 ADD2(a[7],  sW64[ 64 + (I)]); ADD2(a[9],  sW64[ 96 + (I)]); \
                 ADD2(a[10], sW64[128 + (I)]); ADD2(a[11], sW64[160 + (I)]); \
                 ADD2(a[13], sW64[192 + (I)]); ADD2(a[14], sW64[224 + (I)]); \
                 ADD2(a[15], sW64[256 + (I)]); }
#define Y12(I) { ADD2(a[4],  sW64[ 32 + (I)]); ADD2(a[5],  sW64[ 64 + (I)]); \
                 ADD2(a[8],  sW64[128 + (I)]); ADD2(a[9],  sW64[160 + (I)]); \
                 ADD2(a[12], sW64[224 + (I)]); ADD2(a[13], sW64[256 + (I)]); }
#define Y20(I) { ADD2(a[3],  sW64[ 96 + (I)]); ADD2(a[7],  sW64[192 + (I)]); }
#define Y21(I) { ADD2(a[1],  sW64[ 96 + (I)]); ADD2(a[2],  sW64[128 + (I)]); \
                 ADD2(a[3],  sW64[160 + (I)]); ADD2(a[5],  sW64[192 + (I)]); \
                 ADD2(a[6],  sW64[224 + (I)]); ADD2(a[7],  sW64[256 + (I)]); }
#define Y22(I) { ADD2(a[0],  sW64[128 + (I)]); ADD2(a[1],  sW64[160 + (I)]); \
                 ADD2(a[4],  sW64[224 + (I)]); ADD2(a[5],  sW64[256 + (I)]); }
#define VE(I)  { u64 w_ = wb[(I)]; ADD2(acc, w_); }

#define ELOOP3(P, U) { \
    const int c_ = g_cnt2[P]; \
    const uint8_t* lp_ = g_lst2 + (P)*32; \
    int j_ = 0; \
    for (; j_ + 4 <= c_; j_ += 4) { \
        uint32_t q_ = *(const uint32_t*)(lp_ + j_); \
        U((q_      ) & 0xFF) U((q_ >>  8) & 0xFF) \
        U((q_ >> 16) & 0xFF) U((q_ >> 24)       ) \
    } \
    for (; j_ < c_; j_++) U(lp_[j_]) \
}

__global__ void k_conv3() {
    GRID_SYNC();
    __shared__ u64 sW64[9*C2];
    for (int i = threadIdx.x; i < 9*C2*2; i += blockDim.x)
        ((float*)sW64)[i] = g_w3r[i];
    __syncthreads();
    const int task = blockIdx.x*blockDim.x + threadIdx.x;
    const int BT  = FRAMES*30*30;
    const int TOT = BT + FRAMES*241;
    if (task >= TOT) return;
    if (task < BT) {
        const int j  = task % 30;
        const int i  = (task/30) % 30;
        const int tn = task / 900;
        const int fb = tn*P2;
        const int br = 2*i + 2, bc = 2*j + 2;
        u64 a[16];
        #pragma unroll
        for (int k = 0; k < 16; k++) a[k] = 0ull;
        ELOOP3(fb + br*W2 + bc,       Y00)
        ELOOP3(fb + br*W2 + bc-1,     Y01)
        ELOOP3(fb + br*W2 + bc-2,     Y02)
        ELOOP3(fb + (br-1)*W2 + bc,   Y10)
        ELOOP3(fb + (br-1)*W2 + bc-1, Y11)
        ELOOP3(fb + (br-1)*W2 + bc-2, Y12)
        ELOOP3(fb + (br-2)*W2 + bc,   Y20)
        ELOOP3(fb + (br-2)*W2 + bc-1, Y21)
        ELOOP3(fb + (br-2)*W2 + bc-2, Y22)
        const size_t zb = ((size_t)tn*P3 + (4*i)*W3 + 4*j)*2;
        #pragma unroll
        for (int orow = 0; orow < 4; orow++)
            #pragma unroll
            for (int ocol = 0; ocol < 4; ocol++)
                *(u64*)(g_z3 + zb + ((size_t)orow*W3 + ocol)*2) = a[orow*4 + ocol];
    } else {
        const int e  = task - BT;
        const int tn = e / 241;
        const int r  = e % 241;
        int oh, ow;
        if (r < 121) { oh = 120; ow = r; } else { oh = r - 121; ow = 120; }
        int khs[2], ihs[2], nh; int kws[2], iws[2], nw;
        if (oh & 1) { khs[0]=0; ihs[0]=(oh+1)>>1; khs[1]=2; ihs[1]=(oh-1)>>1; nh=2; }
        else        { khs[0]=1; ihs[0]=oh>>1; nh=1; }
        if (ow & 1) { kws[0]=0; iws[0]=(ow+1)>>1; kws[1]=2; iws[1]=(ow-1)>>1; nw=2; }
        else        { kws[0]=1; iws[0]=ow>>1; nw=1; }
        u64 acc = 0ull;
        for (int aa = 0; aa < nh; aa++)
            for (int b = 0; b < nw; b++) {
                const int p = tn*P2 + ihs[aa]*W2 + iws[b];
                const u64* wb = sW64 + (khs[aa]*3 + kws[b])*C2;
                ELOOP3(p, VE)
            }
        *(u64*)(g_z3 + ((size_t)tn*P3 + oh*W3 + ow)*2) = acc;
    }
}

// ---- final LIF (unchanged body): pipelined, bitpacked, ticket-based means ----
__global__ void k_lif3out(float* __restrict__ out, int off) {
    GRID_SYNC();
    const int idx = blockIdx.x*blockDim.x + threadIdx.x;
    const bool valid = (idx < NB*P3);
    int cnt = 0;
    if (valid) {
        const int pix = idx % P3;
        const int n   = idx / P3;
        const size_t a0 = ((size_t)n*P3 + pix)*C3;
        const size_t st = (size_t)NB*P3*C3;
        float cur0=0.f, vol0=0.f, cur1=0.f, vol1=0.f;
        uint32_t bits0 = 0, bits1 = 0;
        u64 buf[4];
        #pragma unroll
        for (int q = 0; q < 4; q++) buf[q] = *(const u64*)(g_z3 + a0 + (size_t)q*st);
        #pragma unroll
        for (int tb = 0; tb < 8; tb++) {
            u64 nxt[4];
            if (tb < 7) {
                #pragma unroll
                for (int q = 0; q < 4; q++)
                    nxt[q] = *(const u64*)(g_z3 + a0 + (size_t)((tb+1)*4 + q)*st);
            }
            #pragma unroll
            for (int q = 0; q < 4; q++) {
                const int t = tb*4 + q;
                float2 zv = *(float2*)&buf[q];
                cur0 = 0.5f*cur0 + zv.x; vol0 = 0.5f*vol0 + cur0;
                cur1 = 0.5f*cur1 + zv.y; vol1 = 0.5f*vol1 + cur1;
                bool s0 = (vol0 >= 1.0f), s1 = (vol1 >= 1.0f);
                vol0 = s0 ? 0.f : vol0;  vol1 = s1 ? 0.f : vol1;
                bits0 |= (s0 ? 1u : 0u) << t;
                bits1 |= (s1 ? 1u : 0u) << t;
            }
            if (tb < 7) {
                #pragma unroll
                for (int q = 0; q < 4; q++) buf[q] = nxt[q];
            }
        }
        cnt = __popc(bits0) + __popc(bits1);
        float4* op0 = (float4*)(out + (((size_t)n*C3 + 0)*P3 + pix)*TT);
        float4* op1 = (float4*)(out + (((size_t)n*C3 + 1)*P3 + pix)*TT);
        #pragma unroll
        for (int q = 0; q < 8; q++) {
            op0[q] = make_float4((float)((bits0 >> (4*q  )) & 1u),
                                 (float)((bits0 >> (4*q+1)) & 1u),
                                 (float)((bits0 >> (4*q+2)) & 1u),
                                 (float)((bits0 >> (4*q+3)) & 1u));
            op1[q] = make_float4((float)((bits1 >> (4*q  )) & 1u),
                                 (float)((bits1 >> (4*q+1)) & 1u),
                                 (float)((bits1 >> (4*q+2)) & 1u),
                                 (float)((bits1 >> (4*q+3)) & 1u));
        }
    }
    cnt = __reduce_add_sync(0xffffffffu, cnt);
    if ((threadIdx.x & 31) == 0 && cnt) atomicAdd(&g_cnt[2], cnt);
    __syncthreads();
    if (threadIdx.x == 0) {
        __threadfence();
        int tk = atomicAdd(&g_ticket, 1);
        if (tk == gridDim.x - 1) {
            out[off+0] = (float)g_cnt[0] * (1.0f / (float)((size_t)NB*C1*P1*TT));
            out[off+1] = (float)g_cnt[1] * (1.0f / (float)((size_t)NB*C2*P2*TT));
            out[off+2] = (float)g_cnt[2] * (1.0f / (float)((size_t)NB*C3*P3*TT));
        }
    }
}

// ---- host: PDL launch helper ----
static void launch_pdl(const void* fn, dim3 grid, dim3 block, int smem,
                       void** args) {
    cudaLaunchConfig_t cfg = {};
    cfg.gridDim = grid;
    cfg.blockDim = block;
    cfg.dynamicSmemBytes = (size_t)smem;
    cfg.stream = 0;
    cudaLaunchAttribute attr[1];
    attr[0].id = cudaLaunchAttributeProgrammaticStreamSerialization;
    attr[0].val.programmaticStreamSerializationAllowed = 1;
    cfg.attrs = attr;
    cfg.numAttrs = 1;
    cudaLaunchKernelExC(&cfg, fn, args);
}

extern "C" void kernel_launch(void* const* d_in, const int* in_sizes, int n_in,
                              void* d_out, int out_size) {
    const float* x  = (const float*)d_in[0];
    const float* w1 = (const float*)d_in[1];
    const float* w2 = (const float*)d_in[2];
    const float* w3 = (const float*)d_in[3];
    float* out = (float*)d_out;

    const int smem1a = 2*C0*C1*4;   // 65536
    const int smem1b = 4*C0*C1*4;   // 131072
    const int smem2  = 9*C1*C2*4;   // 73728
    cudaFuncSetAttribute((const void*)k_conv1a,
                         cudaFuncAttributeMaxDynamicSharedMemorySize, smem1a);
    cudaFuncSetAttribute((const void*)k_conv1b,
                         cudaFuncAttributeMaxDynamicSharedMemorySize, smem1b);
    cudaFuncSetAttribute((const void*)k_conv2,
                         cudaFuncAttributeMaxDynamicSharedMemorySize, smem2);

    const int wtot = 9*C0*C1 + 9*C1*C2 + 9*C2*C3;
    k_prep<<<256 + (wtot + 255)/256, 256>>>(x, w1, w2, w3);

    void* noargs[1] = { 0 };
    launch_pdl((const void*)k_conv1a, dim3(296), dim3(1024), smem1a, (void**)noargs);
    launch_pdl((const void*)k_conv1b, dim3(148), dim3(1024), smem1b, (void**)noargs);
    launch_pdl((const void*)k_lif1,   dim3(961), dim3(128),  0,     (void**)noargs);
    launch_pdl((const void*)k_conv2,  dim3(296), dim3(1024), smem2, (void**)noargs);
    launch_pdl((const void*)k_lif2,   dim3((NB*P2/2 + 7)/8), dim3(256), 0, (void**)noargs);
    launch_pdl((const void*)k_conv3,  dim3((FRAMES*(30*30 + 241) + 255)/256), dim3(256), 0,
               (void**)noargs);
    {
        float* a0 = out;
        int a1 = out_size - 3;
        void* args[2] = { &a0, &a1 };
        launch_pdl((const void*)k_lif3out, dim3((NB*P3 + 255)/256), dim3(256), 0, args);
    }
}

// round 16
// speedup vs baseline: 1.0456x; 1.0229x over previous
#include <cuda_runtime.h>
#include <stdint.h>

#define TT 32
#define NB 4
#define FRAMES (TT*NB)
#define NCH 2              // batches per chunk
#define CHF (TT*NCH)       // frames per chunk = 64

#define C0 128
#define H0 16
#define W0 16
#define C1 64
#define H1 31
#define W1 31
#define C2 32
#define H2 61
#define W2 61
#define C3 2
#define H3 121
#define W3 121

#define P0 (H0*W0)
#define P1 (H1*W1)
#define P2 (H2*W2)
#define P3 (H3*W3)

typedef unsigned long long u64;

__device__ uint8_t g_cnt0[FRAMES*P0];
__device__ uint8_t g_lst0[FRAMES*P0*128];
__device__ float   g_w1r[9*C0*C1];
__device__ float   g_w2r[9*C1*C2];
__device__ float   g_w3r[9*C2*C3];
__device__ float   g_z1[(size_t)FRAMES*P1*C1];
__device__ uint8_t g_cnt1[FRAMES*P1];
__device__ uint8_t g_lst1[FRAMES*P1*64];
__device__ float   g_z2[(size_t)FRAMES*P2*C2];
__device__ uint8_t g_cnt2[FRAMES*P2];
__device__ uint8_t g_lst2[FRAMES*P2*32];
__device__ float   g_z3[(size_t)FRAMES*P3*C3];
__device__ int     g_cnt[3];
__device__ int     g_ticket;

#define ADD2(A, W) asm("add.rn.f32x2 %0, %0, %1;" : "+l"(A) : "l"(W))
#define GRID_SYNC() cudaGridDependencySynchronize()

// ---- merged prep (unchanged) ----
__global__ void k_prep(const float* __restrict__ x, const float* __restrict__ w1,
                       const float* __restrict__ w2, const float* __restrict__ w3) {
    if (blockIdx.x >= 256) {
        int idx = (blockIdx.x - 256)*256 + threadIdx.x;
        if (idx < 3) g_cnt[idx] = 0;
        if (idx == 3) g_ticket = 0;
        if (idx < 9*C0*C1) {
            int co = idx & 63;
            int ci = (idx >> 6) & 127;
            int tap = idx >> 13;
            g_w1r[idx] = 2.0f * w1[(ci*C1 + co)*9 + tap];
        } else if (idx < 9*C0*C1 + 9*C1*C2) {
            int i = idx - 9*C0*C1;
            int co = i & 31;
            int ci = (i >> 5) & 63;
            int tap = i >> 11;
            g_w2r[i] = 2.0f * w2[(ci*C2 + co)*9 + tap];
        } else if (idx < 9*C0*C1 + 9*C1*C2 + 9*C2*C3) {
            int i = idx - (9*C0*C1 + 9*C1*C2);
            int co = i & 1;
            int ci = (i >> 1) & 31;
            int tap = i >> 6;
            g_w3r[i] = 2.0f * w3[(ci*C3 + co)*9 + tap];
        }
        return;
    }
    const int lane = threadIdx.x & 31;
    const int gw = blockIdx.x*8 + (threadIdx.x >> 5);
    const int half = gw & 1;
    const int pp = gw >> 1;
    const int pix = pp % P0;
    const int n   = pp / P0;
    const uint32_t ltmask = (1u << lane) - 1u;
    uint32_t tmask[4];
    #pragma unroll
    for (int w = 0; w < 4; w++) {
        const float4* xp = (const float4*)(x + (((size_t)n*C0 + w*32 + lane)*P0 + pix)*TT)
                           + half*4;
        uint32_t m = 0;
        #pragma unroll
        for (int q = 0; q < 4; q++) {
            float4 vv = xp[q];
            m |= (vv.x >= 0.5f ? 1u : 0u) << (4*q);
            m |= (vv.y >= 0.5f ? 1u : 0u) << (4*q+1);
            m |= (vv.z >= 0.5f ? 1u : 0u) << (4*q+2);
            m |= (vv.w >= 0.5f ? 1u : 0u) << (4*q+3);
        }
        tmask[w] = m;
    }
    #pragma unroll 1
    for (int tt = 0; tt < 16; tt++) {
        const int t = half*16 + tt;
        const int p = (t*NB + n)*P0 + pix;
        uint8_t* lb = g_lst0 + p*128;
        int off = 0;
        #pragma unroll
        for (int w = 0; w < 4; w++) {
            bool s = (tmask[w] >> tt) & 1u;
            uint32_t bal = __ballot_sync(0xffffffffu, s);
            if (s) lb[off + __popc(bal & ltmask)] = (uint8_t)(w*32 + lane);
            off += __popc(bal);
        }
        if (lane == 0) g_cnt0[p] = (uint8_t)off;
    }
}

#define EV1(I) { u64 w_ = wb[(I)*32]; ADD2(acc, w_); }

// ==== layer 1 conv body: chunked by nb0 ====
template<int PH, int PW>
__device__ __forceinline__ void conv1body(float* sW, int firstBlk, int nblk, int nb0) {
    constexpr int NKH = PH ? 2 : 1;
    constexpr int NKW = PW ? 2 : 1;
    constexpr int NT = NKH*NKW;
    for (int i = threadIdx.x; i < NT*C0*C1; i += 1024) {
        int ti = i >> 13;
        int r  = i & 8191;
        int kh = PH ? (ti/NKW)*2 : 1;
        int kw = PW ? (ti%NKW)*2 : 1;
        sW[i] = g_w1r[(kh*3+kw)*8192 + r];
    }
    __syncthreads();
    const int lane = threadIdx.x & 31;
    const int warp = threadIdx.x >> 5;
    constexpr int ROWS = PH ? H0-1 : H0;
    constexpr int COLS = PW ? W0-1 : W0;
    const int tasks = CHF*ROWS*COLS;
    for (int task = (blockIdx.x - firstBlk)*32 + warp; task < tasks; task += nblk*32) {
        const int ocol = task % COLS;
        const int tmp  = task / COLS;
        const int orow = tmp % ROWS;
        const int cf   = tmp / ROWS;
        const int tn   = (cf >> 1)*NB + nb0 + (cf & 1);
        const int fb   = tn*P0;
        int po[NT];
        #pragma unroll
        for (int a = 0; a < NKH; a++) {
            const int ih = PH ? (a == 0 ? orow+1 : orow) : orow;
            #pragma unroll
            for (int b = 0; b < NKW; b++) {
                const int iw = PW ? (b == 0 ? ocol+1 : ocol) : ocol;
                po[a*NKW+b] = fb + ih*W0 + iw;
            }
        }
        u64 acc = 0ull;
        #pragma unroll
        for (int ti = 0; ti < NT; ti++) {
            const int p = po[ti];
            const int c = g_cnt0[p];
            const uint8_t* lp = g_lst0 + p*128;
            const u64* wb = (const u64*)(sW + ti*8192) + lane;
            int j = 0;
            for (; j + 8 <= c; j += 8) {
                uint2 q = *(const uint2*)(lp + j);
                EV1((q.x      ) & 0xFF) EV1((q.x >>  8) & 0xFF)
                EV1((q.x >> 16) & 0xFF) EV1((q.x >> 24)       )
                EV1((q.y      ) & 0xFF) EV1((q.y >>  8) & 0xFF)
                EV1((q.y >> 16) & 0xFF) EV1((q.y >> 24)       )
            }
            if (j + 4 <= c) {
                uint32_t q = *(const uint32_t*)(lp + j);
                EV1((q      ) & 0xFF) EV1((q >>  8) & 0xFF)
                EV1((q >> 16) & 0xFF) EV1((q >> 24)       )
                j += 4;
            }
            for (; j < c; j++) EV1(lp[j]);
        }
        const int oh = PH ? 2*orow+1 : 2*orow;
        const int ow = PW ? 2*ocol+1 : 2*ocol;
        *(u64*)(g_z1 + ((size_t)tn*P1 + oh*W1 + ow)*C1 + 2*lane) = acc;
    }
}

__global__ void __launch_bounds__(1024)
k_conv1a(int nb0) {
    GRID_SYNC();
    extern __shared__ float sW[];
    const int blk = blockIdx.x;
    if (blk < 62)       conv1body<0,0>(sW, 0,   62,  nb0);
    else if (blk < 179) conv1body<0,1>(sW, 62,  117, nb0);
    else                conv1body<1,0>(sW, 179, 117, nb0);
}
__global__ void __launch_bounds__(1024)
k_conv1b(int nb0) {
    GRID_SYNC();
    extern __shared__ float sW[];
    conv1body<1,1>(sW, 0, 148, nb0);
}

// ==== layer 2 conv: 4x4 output-block gather, chunked ====
#define X00(I) { const float* e_ = sWl + (I)*32; acc[15] += e_[0]; }
#define X01(I) { const float* e_ = sWl + (I)*32; acc[13] += e_[0]; acc[14] += e_[2048]; \
                 acc[15] += e_[4096]; }
#define X02(I) { const float* e_ = sWl + (I)*32; acc[12] += e_[2048]; acc[13] += e_[4096]; }
#define X10(I) { const float* e_ = sWl + (I)*32; acc[7] += e_[0]; acc[11] += e_[6144]; \
                 acc[15] += e_[12288]; }
#define X11(I) { const float* e_ = sWl + (I)*32; \
                 acc[5]  += e_[0];     acc[6]  += e_[2048];  acc[7]  += e_[4096]; \
                 acc[9]  += e_[6144];  acc[10] += e_[8192];  acc[11] += e_[10240]; \
                 acc[13] += e_[12288]; acc[14] += e_[14336]; acc[15] += e_[16384]; }
#define X12(I) { const float* e_ = sWl + (I)*32; \
                 acc[4]  += e_[2048];  acc[5]  += e_[4096]; \
                 acc[8]  += e_[8192];  acc[9]  += e_[10240]; \
                 acc[12] += e_[14336]; acc[13] += e_[16384]; }
#define X20(I) { const float* e_ = sWl + (I)*32; acc[3] += e_[6144]; acc[7] += e_[12288]; }
#define X21(I) { const float* e_ = sWl + (I)*32; \
                 acc[1]  += e_[6144];  acc[2]  += e_[8192];  acc[3]  += e_[10240]; \
                 acc[5]  += e_[12288]; acc[6]  += e_[14336]; acc[7]  += e_[16384]; }
#define X22(I) { const float* e_ = sWl + (I)*32; \
                 acc[0]  += e_[8192];  acc[1]  += e_[10240]; \
                 acc[4]  += e_[14336]; acc[5]  += e_[16384]; }
#define UE(I)  { acc0 += wb[(I)*32]; }

#define ELOOP2(P, U) { \
    const int c_ = g_cnt1[P]; \
    const uint8_t* lp_ = g_lst1 + (P)*64; \
    int j_ = 0; \
    for (; j_ + 4 <= c_; j_ += 4) { \
        uint32_t q_ = *(const uint32_t*)(lp_ + j_); \
        U((q_      ) & 0xFF) U((q_ >>  8) & 0xFF) \
        U((q_ >> 16) & 0xFF) U((q_ >> 24)       ) \
    } \
    for (; j_ < c_; j_++) U(lp_[j_]) \
}

__global__ void __launch_bounds__(1024)
k_conv2(int nb0) {
    GRID_SYNC();
    extern __shared__ float sW[];
    for (int i = threadIdx.x; i < 9*C1*C2; i += 1024) sW[i] = g_w2r[i];
    __syncthreads();
    const int lane = threadIdx.x & 31;
    const int warp = threadIdx.x >> 5;
    const float* sWl = sW + lane;
    const int BT  = CHF*15*15;
    const int TOT = BT + CHF*121;
    for (int task = blockIdx.x*32 + warp; task < TOT; task += gridDim.x*32) {
        if (task < BT) {
            const int j  = task % 15;
            const int i  = (task/15) % 15;
            const int cf = task / 225;
            const int tn = (cf >> 1)*NB + nb0 + (cf & 1);
            const int fb = tn*P1;
            const int br = 2*i + 2, bc = 2*j + 2;
            float acc[16];
            #pragma unroll
            for (int k = 0; k < 16; k++) acc[k] = 0.f;
            ELOOP2(fb + br*W1 + bc,       X00)
            ELOOP2(fb + br*W1 + bc-1,     X01)
            ELOOP2(fb + br*W1 + bc-2,     X02)
            ELOOP2(fb + (br-1)*W1 + bc,   X10)
            ELOOP2(fb + (br-1)*W1 + bc-1, X11)
            ELOOP2(fb + (br-1)*W1 + bc-2, X12)
            ELOOP2(fb + (br-2)*W1 + bc,   X20)
            ELOOP2(fb + (br-2)*W1 + bc-1, X21)
            ELOOP2(fb + (br-2)*W1 + bc-2, X22)
            const size_t zb = ((size_t)tn*P2 + (4*i)*W2 + 4*j)*C2 + lane;
            #pragma unroll
            for (int orow = 0; orow < 4; orow++)
                #pragma unroll
                for (int ocol = 0; ocol < 4; ocol++)
                    g_z2[zb + ((size_t)orow*W2 + ocol)*C2] = acc[orow*4 + ocol];
        } else {
            const int e  = task - BT;
            const int cf = e / 121;
            const int tn = (cf >> 1)*NB + nb0 + (cf & 1);
            const int r  = e % 121;
            int oh, ow;
            if (r < 61) { oh = 60; ow = r; } else { oh = r - 61; ow = 60; }
            int khs[2], ihs[2], nh; int kws[2], iws[2], nw;
            if (oh & 1) { khs[0]=0; ihs[0]=(oh+1)>>1; khs[1]=2; ihs[1]=(oh-1)>>1; nh=2; }
            else        { khs[0]=1; ihs[0]=oh>>1; nh=1; }
            if (ow & 1) { kws[0]=0; iws[0]=(ow+1)>>1; kws[1]=2; iws[1]=(ow-1)>>1; nw=2; }
            else        { kws[0]=1; iws[0]=ow>>1; nw=1; }
            const int fb = tn*P1;
            float acc0 = 0.f;
            for (int a = 0; a < nh; a++)
                for (int b = 0; b < nw; b++) {
                    const int p = fb + ihs[a]*W1 + iws[b];
                    const float* wb = sW + (khs[a]*3 + kws[b])*2048 + lane;
                    ELOOP2(p, UE)
                }
            g_z2[((size_t)tn*P2 + oh*W2 + ow)*C2 + lane] = acc0;
        }
    }
}

// ---- LIF layer 1: chunked ----
__global__ void k_lif1(int nb0) {
    GRID_SYNC();
    const int gw = blockIdx.x*4 + (threadIdx.x >> 5);
    if (gw >= NCH*P1) return;
    const int lane = threadIdx.x & 31;
    const int pix = gw % P1;
    const int n   = nb0 + gw / P1;
    const uint32_t ltmask = (1u << lane) - 1u;
    const size_t a0 = ((size_t)n*P1 + pix)*C1 + 2*lane;
    const size_t st = (size_t)NB*P1*C1;
    float cur0=0.f, vol0=0.f, cur1=0.f, vol1=0.f;
    int cnt = 0;
    u64 buf[4];
    #pragma unroll
    for (int q = 0; q < 4; q++) buf[q] = *(const u64*)(g_z1 + a0 + (size_t)q*st);
    #pragma unroll
    for (int tb = 0; tb < 8; tb++) {
        u64 nxt[4];
        if (tb < 7) {
            #pragma unroll
            for (int q = 0; q < 4; q++)
                nxt[q] = *(const u64*)(g_z1 + a0 + (size_t)((tb+1)*4 + q)*st);
        }
        #pragma unroll
        for (int q = 0; q < 4; q++) {
            const int t = tb*4 + q;
            float2 zz = *(float2*)&buf[q];
            cur0 = 0.5f*cur0 + zz.x; vol0 = 0.5f*vol0 + cur0;
            cur1 = 0.5f*cur1 + zz.y; vol1 = 0.5f*vol1 + cur1;
            bool s0 = (vol0 >= 1.0f); vol0 = s0 ? 0.f : vol0;
            bool s1 = (vol1 >= 1.0f); vol1 = s1 ? 0.f : vol1;
            cnt += (s0 ? 1 : 0) + (s1 ? 1 : 0);
            uint32_t b0 = __ballot_sync(0xffffffffu, s0);
            uint32_t b1 = __ballot_sync(0xffffffffu, s1);
            const int p = (t*NB + n)*P1 + pix;
            const int off0 = __popc(b0 & ltmask) + __popc(b1 & ltmask);
            if (s0) g_lst1[p*64 + off0] = (uint8_t)(2*lane);
            if (s1) g_lst1[p*64 + off0 + (s0 ? 1 : 0)] = (uint8_t)(2*lane + 1);
            if (lane == 0) g_cnt1[p] = (uint8_t)(__popc(b0) + __popc(b1));
        }
        if (tb < 7) {
            #pragma unroll
            for (int q = 0; q < 4; q++) buf[q] = nxt[q];
        }
    }
    cnt = __reduce_add_sync(0xffffffffu, cnt);
    if (lane == 0) atomicAdd(&g_cnt[0], cnt);
}

// ---- LIF layer 2: chunked ----
__global__ void k_lif2(int nb0) {
    GRID_SYNC();
    const int gw = blockIdx.x*(blockDim.x >> 5) + (threadIdx.x >> 5);
    const int lane = threadIdx.x & 31;
    const int half = lane >> 4;
    const int j    = lane & 15;
    const int pix2 = gw*2 + half;
    if (pix2 >= NCH*P2) return;
    const int pix = pix2 % P2;
    const int n   = nb0 + pix2 / P2;
    const uint32_t hmask  = half ? 0xFFFF0000u : 0x0000FFFFu;
    const uint32_t ltmask = ((1u << lane) - 1u) & hmask;
    const size_t a0 = ((size_t)n*P2 + pix)*C2 + 2*j;
    const size_t st = (size_t)NB*P2*C2;
    float cur0=0.f, vol0=0.f, cur1=0.f, vol1=0.f;
    int cnt = 0;
    u64 buf[4];
    #pragma unroll
    for (int q = 0; q < 4; q++) buf[q] = *(const u64*)(g_z2 + a0 + (size_t)q*st);
    #pragma unroll
    for (int tb = 0; tb < 8; tb++) {
        u64 nxt[4];
        if (tb < 7) {
            #pragma unroll
            for (int q = 0; q < 4; q++)
                nxt[q] = *(const u64*)(g_z2 + a0 + (size_t)((tb+1)*4 + q)*st);
        }
        #pragma unroll
        for (int q = 0; q < 4; q++) {
            const int t = tb*4 + q;
            float2 zz = *(float2*)&buf[q];
            cur0 = 0.5f*cur0 + zz.x; vol0 = 0.5f*vol0 + cur0;
            cur1 = 0.5f*cur1 + zz.y; vol1 = 0.5f*vol1 + cur1;
            bool s0 = (vol0 >= 1.0f); vol0 = s0 ? 0.f : vol0;
            bool s1 = (vol1 >= 1.0f); vol1 = s1 ? 0.f : vol1;
            cnt += (s0 ? 1 : 0) + (s1 ? 1 : 0);
            uint32_t b0 = __ballot_sync(0xffffffffu, s0) & hmask;
            uint32_t b1 = __ballot_sync(0xffffffffu, s1) & hmask;
            const int p = (t*NB + n)*P2 + pix;
            const int off0 = __popc(b0 & ltmask) + __popc(b1 & ltmask);
            if (s0) g_lst2[p*32 + off0] = (uint8_t)(2*j);
            if (s1) g_lst2[p*32 + off0 + (s0 ? 1 : 0)] = (uint8_t)(2*j + 1);
            if (j == 0) g_cnt2[p] = (uint8_t)(__popc(b0) + __popc(b1));
        }
        if (tb < 7) {
            #pragma unroll
            for (int q = 0; q < 4; q++) buf[q] = nxt[q];
        }
    }
    cnt = __reduce_add_sync(0xffffffffu, cnt);
    if (lane == 0) atomicAdd(&g_cnt[1], cnt);
}

// ==== layer 3 conv: 4x4 output-block gather, chunked ====
#define Y00(I) { ADD2(a[15], sW64[      (I)]); }
#define Y01(I) { ADD2(a[13], sW64[      (I)]); ADD2(a[14], sW64[ 32 + (I)]); \
                 ADD2(a[15], sW64[ 64 + (I)]); }
#define Y02(I) { ADD2(a[12], sW64[ 32 + (I)]); ADD2(a[13], sW64[ 64 + (I)]); }
#define Y10(I) { ADD2(a[7],  sW64[      (I)]); ADD2(a[11], sW64[ 96 + (I)]); \
                 ADD2(a[15], sW64[192 + (I)]); }
#define Y11(I) { ADD2(a[5],  sW64[      (I)]); ADD2(a[6],  sW64[ 32 + (I)]); \
                 ADD2(a[7],  sW64[ 64 + (I)]); ADD2(a[9],  sW64[ 96 + (I)]); \
                 ADD2(a[10], sW64[128 + (I)]); ADD2(a[11], sW64[160 + (I)]); \
                 ADD2(a[13], sW64[192 + (I)]); ADD2(a[14], sW64[224 + (I)]); \
                 ADD2(a[15], sW64[256 + (I)]); }
#define Y12(I) { ADD2(a[4],  sW64[ 32 + (I)]); ADD2(a[5],  sW64[ 64 + (I)]); \
                 ADD2(a[8],  sW64[128 + (I)]); ADD2(a[9],  sW64[160 + (I)]); \
                 ADD2(a[12], sW64[224 + (I)]); ADD2(a[13], sW64[256 + (I)]); }
#define Y20(I) { ADD2(a[3],  sW64[ 96 + (I)]); ADD2(a[7],  sW64[192 + (I)]); }
#define Y21(I) { ADD2(a[1],  sW64[ 96 + (I)]); ADD2(a[2],  sW64[128 + (I)]); \
                 ADD2(a[3],  sW64[160 + (I)]); ADD2(a[5],  sW64[192 + (I)]); \
                 ADD2(a[6],  sW64[224 + (I)]); ADD2(a[7],  sW64[256 + (I)]); }
#define Y22(I) { ADD2(a[0],  sW64[128 + (I)]); ADD2(a[1],  sW64[160 + (I)]); \
                 ADD2(a[4],  sW64[224 + (I)]); ADD2(a[5],  sW64[256 + (I)]); }
#define VE(I)  { u64 w_ = wb[(I)]; ADD2(acc, w_); }

#define ELOOP3(P, U) { \
    const int c_ = g_cnt2[P]; \
    const uint8_t* lp_ = g_lst2 + (P)*32; \
    int j_ = 0; \
    for (; j_ + 4 <= c_; j_ += 4) { \
        uint32_t q_ = *(const uint32_t*)(lp_ + j_); \
        U((q_      ) & 0xFF) U((q_ >>  8) & 0xFF) \
        U((q_ >> 16) & 0xFF) U((q_ >> 24)       ) \
    } \
    for (; j_ < c_; j_++) U(lp_[j_]) \
}

__global__ void k_conv3(int nb0) {
    GRID_SYNC();
    __shared__ u64 sW64[9*C2];
    for (int i = threadIdx.x; i < 9*C2*2; i += blockDim.x)
        ((float*)sW64)[i] = g_w3r[i];
    __syncthreads();
    const int task = blockIdx.x*blockDim.x + threadIdx.x;
    const int BT  = CHF*30*30;
    const int TOT = BT + CHF*241;
    if (task >= TOT) return;
    if (task < BT) {
        const int j  = task % 30;
        const int i  = (task/30) % 30;
        const int cf = task / 900;
        const int tn = (cf >> 1)*NB + nb0 + (cf & 1);
        const int fb = tn*P2;
        const int br = 2*i + 2, bc = 2*j + 2;
        u64 a[16];
        #pragma unroll
        for (int k = 0; k < 16; k++) a[k] = 0ull;
        ELOOP3(fb + br*W2 + bc,       Y00)
        ELOOP3(fb + br*W2 + bc-1,     Y01)
        ELOOP3(fb + br*W2 + bc-2,     Y02)
        ELOOP3(fb + (br-1)*W2 + bc,   Y10)
        ELOOP3(fb + (br-1)*W2 + bc-1, Y11)
        ELOOP3(fb + (br-1)*W2 + bc-2, Y12)
        ELOOP3(fb + (br-2)*W2 + bc,   Y20)
        ELOOP3(fb + (br-2)*W2 + bc-1, Y21)
        ELOOP3(fb + (br-2)*W2 + bc-2, Y22)
        const size_t zb = ((size_t)tn*P3 + (4*i)*W3 + 4*j)*2;
        #pragma unroll
        for (int orow = 0; orow < 4; orow++)
            #pragma unroll
            for (int ocol = 0; ocol < 4; ocol++)
                *(u64*)(g_z3 + zb + ((size_t)orow*W3 + ocol)*2) = a[orow*4 + ocol];
    } else {
        const int e  = task - BT;
        const int cf = e / 241;
        const int tn = (cf >> 1)*NB + nb0 + (cf & 1);
        const int r  = e % 241;
        int oh, ow;
        if (r < 121) { oh = 120; ow = r; } else { oh = r - 121; ow = 120; }
        int khs[2], ihs[2], nh; int kws[2], iws[2], nw;
        if (oh & 1) { khs[0]=0; ihs[0]=(oh+1)>>1; khs[1]=2; ihs[1]=(oh-1)>>1; nh=2; }
        else        { khs[0]=1; ihs[0]=oh>>1; nh=1; }
        if (ow & 1) { kws[0]=0; iws[0]=(ow+1)>>1; kws[1]=2; iws[1]=(ow-1)>>1; nw=2; }
        else        { kws[0]=1; iws[0]=ow>>1; nw=1; }
        u64 acc = 0ull;
        for (int aa = 0; aa < nh; aa++)
            for (int b = 0; b < nw; b++) {
                const int p = tn*P2 + ihs[aa]*W2 + iws[b];
                const u64* wb = sW64 + (khs[aa]*3 + kws[b])*C2;
                ELOOP3(p, VE)
            }
        *(u64*)(g_z3 + ((size_t)tn*P3 + oh*W3 + ow)*2) = acc;
    }
}

// ---- final LIF: chunked; ticket counts across BOTH chunks ----
__global__ void k_lif3out(float* __restrict__ out, int off, int nb0, int tickets) {
    GRID_SYNC();
    const int idx = blockIdx.x*blockDim.x + threadIdx.x;
    const bool valid = (idx < NCH*P3);
    int cnt = 0;
    if (valid) {
        const int pix = idx % P3;
        const int n   = nb0 + idx / P3;
        const size_t a0 = ((size_t)n*P3 + pix)*C3;
        const size_t st = (size_t)NB*P3*C3;
        float cur0=0.f, vol0=0.f, cur1=0.f, vol1=0.f;
        uint32_t bits0 = 0, bits1 = 0;
        u64 buf[4];
        #pragma unroll
        for (int q = 0; q < 4; q++) buf[q] = *(const u64*)(g_z3 + a0 + (size_t)q*st);
        #pragma unroll
        for (int tb = 0; tb < 8; tb++) {
            u64 nxt[4];
            if (tb < 7) {
                #pragma unroll
                for (int q = 0; q < 4; q++)
                    nxt[q] = *(const u64*)(g_z3 + a0 + (size_t)((tb+1)*4 + q)*st);
            }
            #pragma unroll
            for (int q = 0; q < 4; q++) {
                const int t = tb*4 + q;
                float2 zv = *(float2*)&buf[q];
                cur0 = 0.5f*cur0 + zv.x; vol0 = 0.5f*vol0 + cur0;
                cur1 = 0.5f*cur1 + zv.y; vol1 = 0.5f*vol1 + cur1;
                bool s0 = (vol0 >= 1.0f), s1 = (vol1 >= 1.0f);
                vol0 = s0 ? 0.f : vol0;  vol1 = s1 ? 0.f : vol1;
                bits0 |= (s0 ? 1u : 0u) << t;
                bits1 |= (s1 ? 1u : 0u) << t;
            }
            if (tb < 7) {
                #pragma unroll
                for (int q = 0; q < 4; q++) buf[q] = nxt[q];
            }
        }
        cnt = __popc(bits0) + __popc(bits1);
        float4* op0 = (float4*)(out + (((size_t)n*C3 + 0)*P3 + pix)*TT);
        float4* op1 = (float4*)(out + (((size_t)n*C3 + 1)*P3 + pix)*TT);
        #pragma unroll
        for (int q = 0; q < 8; q++) {
            op0[q] = make_float4((float)((bits0 >> (4*q  )) & 1u),
                                 (float)((bits0 >> (4*q+1)) & 1u),
                                 (float)((bits0 >> (4*q+2)) & 1u),
                                 (float)((bits0 >> (4*q+3)) & 1u));
            op1[q] = make_float4((float)((bits1 >> (4*q  )) & 1u),
                                 (float)((bits1 >> (4*q+1)) & 1u),
                                 (float)((bits1 >> (4*q+2)) & 1u),
                                 (float)((bits1 >> (4*q+3)) & 1u));
        }
    }
    cnt = __reduce_add_sync(0xffffffffu, cnt);
    if ((threadIdx.x & 31) == 0 && cnt) atomicAdd(&g_cnt[2], cnt);
    __syncthreads();
    if (threadIdx.x == 0) {
        __threadfence();
        int tk = atomicAdd(&g_ticket, 1);
        if (tk == tickets - 1) {
            out[off+0] = (float)g_cnt[0] * (1.0f / (float)((size_t)NB*C1*P1*TT));
            out[off+1] = (float)g_cnt[1] * (1.0f / (float)((size_t)NB*C2*P2*TT));
            out[off+2] = (float)g_cnt[2] * (1.0f / (float)((size_t)NB*C3*P3*TT));
        }
    }
}

// ---- host: PDL launch helper ----
static void launch_pdl(cudaStream_t s, const void* fn, dim3 grid, dim3 block,
                       int smem, void** args) {
    cudaLaunchConfig_t cfg = {};
    cfg.gridDim = grid;
    cfg.blockDim = block;
    cfg.dynamicSmemBytes = (size_t)smem;
    cfg.stream = s;
    cudaLaunchAttribute attr[1];
    attr[0].id = cudaLaunchAttributeProgrammaticStreamSerialization;
    attr[0].val.programmaticStreamSerializationAllowed = 1;
    cfg.attrs = attr;
    cfg.numAttrs = 1;
    cudaLaunchKernelExC(&cfg, fn, args);
}

extern "C" void kernel_launch(void* const* d_in, const int* in_sizes, int n_in,
                              void* d_out, int out_size) {
    const float* x  = (const float*)d_in[0];
    const float* w1 = (const float*)d_in[1];
    const float* w2 = (const float*)d_in[2];
    const float* w3 = (const float*)d_in[3];
    float* out = (float*)d_out;

    const int smem1a = 2*C0*C1*4;
    const int smem1b = 4*C0*C1*4;
    const int smem2  = 9*C1*C2*4;
    cudaFuncSetAttribute((const void*)k_conv1a,
                         cudaFuncAttributeMaxDynamicSharedMemorySize, smem1a);
    cudaFuncSetAttribute((const void*)k_conv1b,
                         cudaFuncAttributeMaxDynamicSharedMemorySize, smem1b);
    cudaFuncSetAttribute((const void*)k_conv2,
                         cudaFuncAttributeMaxDynamicSharedMemorySize, smem2);

    const int wtot = 9*C0*C1 + 9*C1*C2 + 9*C2*C3;
    k_prep<<<256 + (wtot + 255)/256, 256>>>(x, w1, w2, w3);

    // fork two chunk streams off the capture stream
    cudaStream_t s1, s2;
    cudaStreamCreateWithFlags(&s1, cudaStreamNonBlocking);
    cudaStreamCreateWithFlags(&s2, cudaStreamNonBlocking);
    cudaEvent_t e0, e1, e2;
    cudaEventCreateWithFlags(&e0, cudaEventDisableTiming);
    cudaEventCreateWithFlags(&e1, cudaEventDisableTiming);
    cudaEventCreateWithFlags(&e2, cudaEventDisableTiming);
    cudaEventRecord(e0, 0);
    cudaStreamWaitEvent(s1, e0, 0);
    cudaStreamWaitEvent(s2, e0, 0);

    const dim3 gl1((NCH*P1 + 3)/4), bl1(128);
    const dim3 gl2((NCH*P2/2 + 7)/8), bl2(256);
    const dim3 gc3((CHF*(30*30 + 241) + 255)/256), bc3(256);
    const int  gl3 = (NCH*P3 + 255)/256;
    const int  tickets = 2*gl3;

    cudaStream_t ss[2] = { s1, s2 };
    int nb0s[2] = { 0, NCH };
    for (int c = 0; c < 2; c++) {
        cudaStream_t s = ss[c];
        void* a[1] = { &nb0s[c] };
        launch_pdl(s, (const void*)k_conv1a, dim3(296), dim3(1024), smem1a, a);
        launch_pdl(s, (const void*)k_conv1b, dim3(148), dim3(1024), smem1b, a);
        launch_pdl(s, (const void*)k_lif1,   gl1, bl1, 0, a);
        launch_pdl(s, (const void*)k_conv2,  dim3(296), dim3(1024), smem2, a);
        launch_pdl(s, (const void*)k_lif2,   gl2, bl2, 0, a);
        launch_pdl(s, (const void*)k_conv3,  gc3, bc3, 0, a);
        {
            float* a0 = out;
            int a1 = out_size - 3;
            int a2 = nb0s[c];
            int a3 = tickets;
            void* args[4] = { &a0, &a1, &a2, &a3 };
            launch_pdl(s, (const void*)k_lif3out, dim3(gl3), dim3(256), 0, args);
        }
    }

    cudaEventRecord(e1, s1);
    cudaEventRecord(e2, s2);
    cudaStreamWaitEvent(0, e1, 0);
    cudaStreamWaitEvent(0, e2, 0);
    cudaEventDestroy(e0);
    cudaEventDestroy(e1);
    cudaEventDestroy(e2);
    cudaStreamDestroy(s1);
    cudaStreamDestroy(s2);
}